// round 3
// baseline (speedup 1.0000x reference)
#include <cuda_runtime.h>

#define Bc 4
#define Hc 16
#define Sc 4096
#define Dc 64
#define BHc (Bc*Hc)        // 64
#define NCHUNK 16
#define CHUNK (Sc/NCHUNK)  // 256
#define TS 32

// Scratch (allocation-free per harness rules)
__device__ float g_pKV[NCHUNK][BHc][Dc*Dc];  // partial KV per S-chunk
__device__ float g_pKs[NCHUNK][BHc][Dc];     // partial Ksum per S-chunk
__device__ float g_KV[BHc][Dc*Dc];           // reduced KV
__device__ float g_Ks[BHc][Dc];              // reduced Ksum

typedef unsigned long long u64;

__device__ __forceinline__ u64 pack2(float lo, float hi){
    u64 r; asm("mov.b64 %0, {%1,%2};" : "=l"(r) : "f"(lo), "f"(hi)); return r;
}
__device__ __forceinline__ void unpack2(u64 v, float &lo, float &hi){
    asm("mov.b64 {%0,%1}, %2;" : "=f"(lo), "=f"(hi) : "l"(v));
}
// packed dual-fp32 FMA (FFMA2 in SASS; only reachable via PTX fma.rn.f32x2)
__device__ __forceinline__ void fma2(u64 &d, u64 a, u64 b){
    asm("fma.rn.f32x2 %0, %1, %2, %0;" : "+l"(d) : "l"(a), "l"(b));
}
// elu(x)+1 feature map
__device__ __forceinline__ float feat(float x){
    return x > 0.f ? x + 1.f : __expf(x);
}

// ---------------------------------------------------------------------------
// Phase 1: partial KV[d][e] = sum_s Kf[s][d]*V[s][e], partial Ksum[d]
// grid (BHc, NCHUNK), 128 threads. Thread tile 4(d) x 8(e).
// K stored in smem as DUPLICATED f32 pairs -> FFMA2 multiplier via LDS.128,
// zero register MOVs in the inner loop.
// ---------------------------------------------------------------------------
__global__ __launch_bounds__(128) void phase1_kernel(const float* __restrict__ K,
                                                     const float* __restrict__ V,
                                                     const float* __restrict__ mask){
    __shared__ __align__(16) u64   sKd[TS][Dc];   // dup pairs {k,k}, 16KB
    __shared__ __align__(16) float sV [TS][Dc];   // 8KB
    __shared__ float ksP[4][Dc];                  // per-warp ksum partials

    const int bh = blockIdx.x, ch = blockIdx.y;
    const int t  = threadIdx.x;
    const float* Kp = K    + ((size_t)bh*Sc + (size_t)ch*CHUNK)*Dc;
    const float* Vp = V    + ((size_t)bh*Sc + (size_t)ch*CHUNK)*Dc;
    const float* Mp = mask + (size_t)bh*Sc + (size_t)ch*CHUNK;

    // compute-tile mapping: 16 d-groups x 8 e-groups
    const int dy = t >> 3;            // 0..15
    const int ex = t & 7;             // 0..7
    const int d0 = dy*4, e0 = ex*8;

    // loader mapping
    const int lw   = t >> 5;          // warp 0..3
    const int lane = t & 31;

    u64 acc[4][4];
    #pragma unroll
    for (int i=0;i<4;i++)
        #pragma unroll
        for (int j=0;j<4;j++) acc[i][j]=pack2(0.f,0.f);

    float ksA = 0.f, ksB = 0.f;       // partial Ksum for d=2*lane, 2*lane+1

    for (int st = 0; st < CHUNK; st += TS){
        // --- load K (dup pairs, conflict-free STS.128) + accumulate ksum ---
        #pragma unroll
        for (int p = 0; p < 8; p++){
            int r = lw*8 + p;                  // warp lw owns rows lw*8..lw*8+7
            int s = st + r;
            float m = Mp[s];
            float2 k2 = *(const float2*)(Kp + (size_t)s*Dc + lane*2);
            float a = feat(k2.x)*m;
            float b = feat(k2.y)*m;
            ksA += a; ksB += b;
            *(float4*)&sKd[r][lane*2] = make_float4(a,a,b,b);
        }
        // --- load V (float4, conflict-free) ---
        {
            const int vr = t >> 4, vc = (t & 15)*4;
            #pragma unroll
            for (int p = 0; p < 4; p++){
                int r = vr + 8*p;
                int s = st + r;
                *(float4*)&sV[r][vc] = *(const float4*)(Vp + (size_t)s*Dc + vc);
            }
        }
        __syncthreads();

        // --- main GEMM: per s: 2 LDS.128 (k dup) + 2 LDS.128 (v) + 16 FFMA2 ---
        #pragma unroll
        for (int s = 0; s < TS; s++){
            ulonglong2 kA = *(const ulonglong2*)&sKd[s][d0];     // dup(k[d0]),dup(k[d0+1])
            ulonglong2 kB = *(const ulonglong2*)&sKd[s][d0+2];
            ulonglong2 vA = *(const ulonglong2*)&sV[s][e0];      // pairs (e0,e0+1),(e0+2,e0+3)
            ulonglong2 vB = *(const ulonglong2*)&sV[s][e0+4];
            fma2(acc[0][0], kA.x, vA.x); fma2(acc[0][1], kA.x, vA.y);
            fma2(acc[0][2], kA.x, vB.x); fma2(acc[0][3], kA.x, vB.y);
            fma2(acc[1][0], kA.y, vA.x); fma2(acc[1][1], kA.y, vA.y);
            fma2(acc[1][2], kA.y, vB.x); fma2(acc[1][3], kA.y, vB.y);
            fma2(acc[2][0], kB.x, vA.x); fma2(acc[2][1], kB.x, vA.y);
            fma2(acc[2][2], kB.x, vB.x); fma2(acc[2][3], kB.x, vB.y);
            fma2(acc[3][0], kB.y, vA.x); fma2(acc[3][1], kB.y, vA.y);
            fma2(acc[3][2], kB.y, vB.x); fma2(acc[3][3], kB.y, vB.y);
        }
        __syncthreads();
    }

    // --- epilogue: partial KV (store packed pairs directly) ---
    float* outKV = g_pKV[ch][bh];
    #pragma unroll
    for (int i = 0; i < 4; i++){
        *(ulonglong2*)(outKV + (size_t)(d0+i)*Dc + e0    ) = make_ulonglong2(acc[i][0], acc[i][1]);
        *(ulonglong2*)(outKV + (size_t)(d0+i)*Dc + e0 + 4) = make_ulonglong2(acc[i][2], acc[i][3]);
    }
    // --- ksum partials: warp-local d = 2*lane(,+1), reduce over 4 warps ---
    ksP[lw][lane*2]   = ksA;
    ksP[lw][lane*2+1] = ksB;
    __syncthreads();
    if (t < Dc){
        float s = ksP[0][t] + ksP[1][t] + ksP[2][t] + ksP[3][t];
        g_pKs[ch][bh][t] = s;
    }
}

// ---------------------------------------------------------------------------
// Reduce partials
// ---------------------------------------------------------------------------
__global__ void reduce_kernel(){
    const int idx = blockIdx.x*blockDim.x + threadIdx.x;
    const int nKV = BHc*Dc*Dc;
    if (idx < nKV){
        int bh = idx / (Dc*Dc), off = idx % (Dc*Dc);
        float s = 0.f;
        #pragma unroll
        for (int c = 0; c < NCHUNK; c++) s += g_pKV[c][bh][off];
        g_KV[bh][off] = s;
    } else {
        int j = idx - nKV;
        if (j < BHc*Dc){
            int bh = j / Dc, d = j % Dc;
            float s = 0.f;
            #pragma unroll
            for (int c = 0; c < NCHUNK; c++) s += g_pKs[c][bh][d];
            g_Ks[bh][d] = s;
        }
    }
}

// ---------------------------------------------------------------------------
// Phase 2: out[s][e] = Z[s] * sum_d Qf[s][d] * KV[d][e]
// grid (BHc, Sc/64), 128 threads. 64 s-rows/CTA. Thread tile 4(s) x 8(e).
// Qf is staged row-major, then rebuilt as DUPLICATED transposed pairs sQd[d][s]
// with conflict-free writes; inner loop has zero MOVs.
// ---------------------------------------------------------------------------
__global__ __launch_bounds__(128) void phase2_kernel(const float* __restrict__ Q,
                                                     float* __restrict__ out){
    __shared__ __align__(16) float sQ [64][Dc+1];  // staging (feat applied), pad->2-way reads
    __shared__ __align__(16) u64   sQd[Dc][64];    // dup transposed {q,q}, 32KB
    __shared__ __align__(16) float sKV[Dc][Dc];    // 16KB
    __shared__ float sKsum[Dc];
    __shared__ float sZ[64];

    const int bh = blockIdx.x, sb = blockIdx.y;
    const int t  = threadIdx.x;
    const float* Qp = Q + ((size_t)bh*Sc + (size_t)sb*64)*Dc;

    // --- stage Qf row-major ---
    {
        const int lr = t >> 4, lc = (t & 15)*4;
        #pragma unroll
        for (int p = 0; p < 8; p++){
            int r = lr + 8*p;
            float4 q4 = *(const float4*)(Qp + (size_t)r*Dc + lc);
            sQ[r][lc+0] = feat(q4.x);
            sQ[r][lc+1] = feat(q4.y);
            sQ[r][lc+2] = feat(q4.z);
            sQ[r][lc+3] = feat(q4.w);
        }
    }
    // --- load KV + Ksum ---
    {
        const float* kvp = g_KV[bh];
        #pragma unroll
        for (int p = 0; p < 8; p++){
            int i = t + 128*p;
            *(((float4*)&sKV[0][0]) + i) = *(((const float4*)kvp) + i);
        }
        if (t < Dc) sKsum[t] = g_Ks[bh][t];
    }
    __syncthreads();

    // --- build duplicated transposed Q: sQd[d][s] = {Qf[s][d], Qf[s][d]} ---
    {
        const int lw = t >> 5, lane = t & 31;
        #pragma unroll
        for (int p = 0; p < 16; p++){
            int d = lw + 4*p;
            float q0 = sQ[2*lane  ][d];
            float q1 = sQ[2*lane+1][d];
            *(float4*)&sQd[d][2*lane] = make_float4(q0,q0,q1,q1);  // conflict-free STS.128
        }
    }
    // --- Z per s-row ---
    if (t < 64){
        float z = 0.f;
        #pragma unroll 16
        for (int d = 0; d < Dc; d++) z += sQ[t][d] * sKsum[d];
        sZ[t] = 1.f / z;
    }
    __syncthreads();

    // compute-tile mapping: 16 s-groups x 8 e-groups
    const int sy = t >> 3;            // 0..15
    const int ex = t & 7;             // 0..7
    const int s0 = sy*4, e0 = ex*8;

    u64 acc[4][4];
    #pragma unroll
    for (int i=0;i<4;i++)
        #pragma unroll
        for (int j=0;j<4;j++) acc[i][j]=pack2(0.f,0.f);

    #pragma unroll 16
    for (int d = 0; d < Dc; d++){
        ulonglong2 qA = *(const ulonglong2*)&sQd[d][s0];      // dup(q[s0]),dup(q[s0+1])
        ulonglong2 qB = *(const ulonglong2*)&sQd[d][s0+2];
        ulonglong2 vA = *(const ulonglong2*)&sKV[d][e0];
        ulonglong2 vB = *(const ulonglong2*)&sKV[d][e0+4];
        fma2(acc[0][0], qA.x, vA.x); fma2(acc[0][1], qA.x, vA.y);
        fma2(acc[0][2], qA.x, vB.x); fma2(acc[0][3], qA.x, vB.y);
        fma2(acc[1][0], qA.y, vA.x); fma2(acc[1][1], qA.y, vA.y);
        fma2(acc[1][2], qA.y, vB.x); fma2(acc[1][3], qA.y, vB.y);
        fma2(acc[2][0], qB.x, vA.x); fma2(acc[2][1], qB.x, vA.y);
        fma2(acc[2][2], qB.x, vB.x); fma2(acc[2][3], qB.x, vB.y);
        fma2(acc[3][0], qB.y, vA.x); fma2(acc[3][1], qB.y, vA.y);
        fma2(acc[3][2], qB.y, vB.x); fma2(acc[3][3], qB.y, vB.y);
    }

    #pragma unroll
    for (int i = 0; i < 4; i++){
        float z = sZ[s0+i];
        float r0,r1,r2,r3,r4,r5,r6,r7;
        unpack2(acc[i][0], r0, r1);
        unpack2(acc[i][1], r2, r3);
        unpack2(acc[i][2], r4, r5);
        unpack2(acc[i][3], r6, r7);
        float* op = out + ((size_t)bh*Sc + (size_t)sb*64 + s0+i)*Dc + e0;
        *(float4*)(op    ) = make_float4(r0*z, r1*z, r2*z, r3*z);
        *(float4*)(op + 4) = make_float4(r4*z, r5*z, r6*z, r7*z);
    }
}

// ---------------------------------------------------------------------------
extern "C" void kernel_launch(void* const* d_in, const int* in_sizes, int n_in,
                              void* d_out, int out_size){
    const float* Q    = (const float*)d_in[0];
    const float* K    = (const float*)d_in[1];
    const float* V    = (const float*)d_in[2];
    const float* mask = (const float*)d_in[3];
    float* out = (float*)d_out;

    phase1_kernel<<<dim3(BHc, NCHUNK), 128>>>(K, V, mask);

    const int total = BHc*Dc*Dc + BHc*Dc;
    reduce_kernel<<<(total + 255)/256, 256>>>();

    phase2_kernel<<<dim3(BHc, Sc/64), 128>>>(Q, out);
}

// round 5
// speedup vs baseline: 2.2620x; 2.2620x over previous
#include <cuda_runtime.h>

typedef unsigned int u32;

#define Sc 4096
#define Dc 64
#define BHc 64
#define NCHUNK 16
#define CHUNK (Sc/NCHUNK)   // 256

__device__ float g_pKV[NCHUNK][BHc][Dc*Dc];  // f32 partial KV
__device__ float g_pKs[NCHUNK][BHc][Dc];     // f32 partial Ksum
__device__ u32   g_KV[BHc][Dc*Dc];           // reduced KV (tf32 bits)
__device__ u32   g_Ks[BHc][Dc];              // reduced Ksum (tf32 bits)

__device__ __forceinline__ u32 to_tf32(float f){
    u32 r; asm("cvt.rna.tf32.f32 %0, %1;" : "=r"(r) : "f"(f)); return r;
}
__device__ __forceinline__ void mma8(float c[4], u32 a0, u32 a1, u32 a2, u32 a3,
                                     u32 b0, u32 b1){
    asm volatile("mma.sync.aligned.m16n8k8.row.col.f32.tf32.tf32.f32 "
        "{%0,%1,%2,%3}, {%4,%5,%6,%7}, {%8,%9}, {%0,%1,%2,%3};"
        : "+f"(c[0]), "+f"(c[1]), "+f"(c[2]), "+f"(c[3])
        : "r"(a0), "r"(a1), "r"(a2), "r"(a3), "r"(b0), "r"(b1));
}
__device__ __forceinline__ float feat(float x){
    return x > 0.f ? x + 1.f : __expf(x);
}

// ---------------------------------------------------------------------------
// Phase 1: partial KV[d][e] = sum_s Kf[s][d] V[s][e]  (+Ksum via ones column).
// grid (BHc, NCHUNK), 128 threads. Warp w: d-rows [16w,16w+16), 9 n-tiles.
// ---------------------------------------------------------------------------
__global__ __launch_bounds__(128) void phase1_kernel(const float* __restrict__ K,
                                                     const float* __restrict__ V,
                                                     const float* __restrict__ M){
    __shared__ u32 sK[32][72];   // Kf tf32, stride 72 -> A-frag banks 8*tig+g
    __shared__ u32 sV[32][72];   // V tf32 + ones col 64, zeros 65..71

    const int bh = blockIdx.x, ch = blockIdx.y;
    const int t = threadIdx.x;
    const int warp = t >> 5, lane = t & 31;
    const int g = lane >> 2, tig = lane & 3;

    const float* Kp = K + ((size_t)bh*Sc + (size_t)ch*CHUNK)*Dc;
    const float* Vp = V + ((size_t)bh*Sc + (size_t)ch*CHUNK)*Dc;
    const float* Mp = M + (size_t)bh*Sc + (size_t)ch*CHUNK;

    if (t < 32){
        sV[t][64] = 0x3F800000u;         // 1.0f (exact in tf32)
        #pragma unroll
        for (int j = 65; j < 72; j++) sV[t][j] = 0u;
    }

    float acc[9][4];
    #pragma unroll
    for (int n = 0; n < 9; n++)
        #pragma unroll
        for (int i = 0; i < 4; i++) acc[n][i] = 0.f;

    const int srow = t >> 2;             // 0..31
    const int dq = (t & 3) * 16;

    for (int blk = 0; blk < CHUNK/32; blk++){
        __syncthreads();                 // prev compute done before overwrite
        const int s = blk*32 + srow;
        const float m = Mp[s];
        const float* kr = Kp + (size_t)s*Dc + dq;
        const float* vr = Vp + (size_t)s*Dc + dq;
        #pragma unroll
        for (int i = 0; i < 4; i++){
            float4 k4 = *(const float4*)(kr + 4*i);
            float4 v4 = *(const float4*)(vr + 4*i);
            uint4 ku = make_uint4(to_tf32(feat(k4.x)*m), to_tf32(feat(k4.y)*m),
                                  to_tf32(feat(k4.z)*m), to_tf32(feat(k4.w)*m));
            uint4 vu = make_uint4(to_tf32(v4.x), to_tf32(v4.y),
                                  to_tf32(v4.z), to_tf32(v4.w));
            *(uint4*)&sK[srow][dq + 4*i] = ku;
            *(uint4*)&sV[srow][dq + 4*i] = vu;
        }
        __syncthreads();

        const int d0 = warp*16;
        #pragma unroll
        for (int ks = 0; ks < 4; ks++){
            const int s0 = ks*8;
            u32 a0 = sK[s0+tig  ][d0+g  ];
            u32 a1 = sK[s0+tig  ][d0+g+8];
            u32 a2 = sK[s0+tig+4][d0+g  ];
            u32 a3 = sK[s0+tig+4][d0+g+8];
            #pragma unroll
            for (int nt = 0; nt < 9; nt++){
                u32 b0 = sV[s0+tig  ][nt*8+g];
                u32 b1 = sV[s0+tig+4][nt*8+g];
                mma8(acc[nt], a0, a1, a2, a3, b0, b1);
            }
        }
    }

    // epilogue
    const int d0 = warp*16;
    float* dst = g_pKV[ch][bh];
    #pragma unroll
    for (int nt = 0; nt < 8; nt++){
        const int e = nt*8 + 2*tig;
        *(float2*)(dst + (size_t)(d0+g  )*Dc + e) = make_float2(acc[nt][0], acc[nt][1]);
        *(float2*)(dst + (size_t)(d0+g+8)*Dc + e) = make_float2(acc[nt][2], acc[nt][3]);
    }
    if (tig == 0){                        // ones-column tile: col 64 = Ksum
        g_pKs[ch][bh][d0+g  ] = acc[8][0];
        g_pKs[ch][bh][d0+g+8] = acc[8][2];
    }
}

// ---------------------------------------------------------------------------
// Reduce partials; emit tf32 bits for phase2 operands.
// ---------------------------------------------------------------------------
__global__ __launch_bounds__(256) void reduce_kernel(){
    const int bh = blockIdx.x, t = threadIdx.x;
    for (int i = t; i < Dc*Dc; i += 256){
        float s = 0.f;
        #pragma unroll
        for (int c = 0; c < NCHUNK; c++) s += g_pKV[c][bh][i];
        g_KV[bh][i] = to_tf32(s);
    }
    if (t < Dc){
        float s = 0.f;
        #pragma unroll
        for (int c = 0; c < NCHUNK; c++) s += g_pKs[c][bh][t];
        g_Ks[bh][t] = to_tf32(s);
    }
}

// ---------------------------------------------------------------------------
// Phase 2: out[s][e] = Z[s] * sum_d Qf[s][d] KV[d][e]; D[s][64] = 1/Z.
// grid (BHc, Sc/64), 128 threads. Warp w: s-rows [16w,16w+16), 9 n-tiles.
// ---------------------------------------------------------------------------
__global__ __launch_bounds__(128) void phase2_kernel(const float* __restrict__ Q,
                                                     float* __restrict__ out){
    __shared__ u32 sQ[64][68];   // Qf tf32, stride 68 -> A-frag banks 4g+tig
    __shared__ u32 sB[64][72];   // [d][e'] : KV cols 0..63, Ksum col 64, 0s 65..71

    const int bh = blockIdx.x, sb = blockIdx.y;
    const int t = threadIdx.x;
    const int warp = t >> 5, lane = t & 31;
    const int g = lane >> 2, tig = lane & 3;

    // stage B (KV + Ksum column)
    for (int i = t; i < Dc*Dc/4; i += 128){
        const int d = i >> 4, e4 = (i & 15) * 4;
        *(uint4*)&sB[d][e4] = *(const uint4*)&g_KV[bh][(size_t)d*Dc + e4];
    }
    if (t < Dc){
        sB[t][64] = g_Ks[bh][t];
        #pragma unroll
        for (int j = 65; j < 72; j++) sB[t][j] = 0u;
    }
    // stage Qf
    {
        const int r = t >> 2, cq = (t & 3) * 16;
        #pragma unroll
        for (int p = 0; p < 2; p++){
            const float* qr = Q + ((size_t)bh*Sc + (size_t)sb*64 + r + 32*p)*Dc + cq;
            #pragma unroll
            for (int i = 0; i < 4; i++){
                float4 q4 = *(const float4*)(qr + 4*i);
                uint4 qu = make_uint4(to_tf32(feat(q4.x)), to_tf32(feat(q4.y)),
                                      to_tf32(feat(q4.z)), to_tf32(feat(q4.w)));
                *(uint4*)&sQ[r + 32*p][cq + 4*i] = qu;
            }
        }
    }
    __syncthreads();

    float acc[9][4];
    #pragma unroll
    for (int n = 0; n < 9; n++)
        #pragma unroll
        for (int i = 0; i < 4; i++) acc[n][i] = 0.f;

    const int m0 = warp*16;
    #pragma unroll
    for (int ks = 0; ks < 8; ks++){
        const int k0 = ks*8;
        u32 a0 = sQ[m0+g  ][k0+tig  ];
        u32 a1 = sQ[m0+g+8][k0+tig  ];
        u32 a2 = sQ[m0+g  ][k0+tig+4];
        u32 a3 = sQ[m0+g+8][k0+tig+4];
        #pragma unroll
        for (int nt = 0; nt < 9; nt++){
            u32 b0 = sB[k0+tig  ][nt*8+g];
            u32 b1 = sB[k0+tig+4][nt*8+g];
            mma8(acc[nt], a0, a1, a2, a3, b0, b1);
        }
    }

    // normalization: denominator lives in n-tile 8, col 64 (tig==0 lanes)
    const float dz0 = __shfl_sync(0xffffffffu, acc[8][0], lane & 28);
    const float dz1 = __shfl_sync(0xffffffffu, acc[8][2], lane & 28);
    const float z0 = 1.f / dz0;
    const float z1 = 1.f / dz1;

    float* op = out + ((size_t)bh*Sc + (size_t)sb*64)*Dc;
    #pragma unroll
    for (int nt = 0; nt < 8; nt++){
        const int e = nt*8 + 2*tig;
        *(float2*)(op + (size_t)(m0+g  )*Dc + e) = make_float2(acc[nt][0]*z0, acc[nt][1]*z0);
        *(float2*)(op + (size_t)(m0+g+8)*Dc + e) = make_float2(acc[nt][2]*z1, acc[nt][3]*z1);
    }
}

// ---------------------------------------------------------------------------
extern "C" void kernel_launch(void* const* d_in, const int* in_sizes, int n_in,
                              void* d_out, int out_size){
    const float* Q    = (const float*)d_in[0];
    const float* K    = (const float*)d_in[1];
    const float* V    = (const float*)d_in[2];
    const float* mask = (const float*)d_in[3];
    float* out = (float*)d_out;

    phase1_kernel<<<dim3(BHc, NCHUNK), 128>>>(K, V, mask);
    reduce_kernel<<<BHc, 256>>>();
    phase2_kernel<<<dim3(BHc, Sc/64), 128>>>(Q, out);
}

// round 7
// speedup vs baseline: 2.3539x; 1.0406x over previous
#include <cuda_runtime.h>

typedef unsigned int u32;

#define Sc 4096
#define Dc 64
#define BHc 64
#define NCHUNK 16
#define CHUNK (Sc/NCHUNK)   // 256
#define NB (CHUNK/32)       // 8 blocks of 32 s-rows

__device__ float g_pKV[NCHUNK][BHc][Dc*Dc];  // f32 partial KV
__device__ float g_pKs[NCHUNK][BHc][Dc];     // f32 partial Ksum
__device__ float g_KV[BHc][Dc*Dc];           // reduced KV (f32)
__device__ float g_Ks[BHc][Dc];              // reduced Ksum (f32)

__device__ __forceinline__ u32 to_tf32(float f){
    u32 r; asm("cvt.rna.tf32.f32 %0, %1;" : "=r"(r) : "f"(f)); return r;
}
__device__ __forceinline__ void mma8(float c[4], u32 a0, u32 a1, u32 a2, u32 a3,
                                     u32 b0, u32 b1){
    asm volatile("mma.sync.aligned.m16n8k8.row.col.f32.tf32.tf32.f32 "
        "{%0,%1,%2,%3}, {%4,%5,%6,%7}, {%8,%9}, {%0,%1,%2,%3};"
        : "+f"(c[0]), "+f"(c[1]), "+f"(c[2]), "+f"(c[3])
        : "r"(a0), "r"(a1), "r"(a2), "r"(a3), "r"(b0), "r"(b1));
}
__device__ __forceinline__ float feat(float x){
    return x > 0.f ? x + 1.f : __expf(x);
}
__device__ __forceinline__ u32 smem_u32(const void* p){
    u32 a; asm("{ .reg .u64 t; cvta.to.shared.u64 t, %1; cvt.u32.u64 %0, t; }" : "=r"(a) : "l"(p));
    return a;
}
__device__ __forceinline__ void cp16(u32 dst, const float* src){
    asm volatile("cp.async.cg.shared.global [%0], [%1], 16;" :: "r"(dst), "l"(src) : "memory");
}
#define CP_COMMIT() asm volatile("cp.async.commit_group;" ::: "memory")

// ---------------------------------------------------------------------------
// Phase 1: partial KV[d][e] = sum_s Kf[s][d] V[s][e] (+Ksum via ones column).
// grid (BHc, NCHUNK), 128 threads. cp.async double-buffered; RNA cvt at frag.
// ---------------------------------------------------------------------------
__global__ __launch_bounds__(128) void phase1_kernel(const float* __restrict__ K,
                                                     const float* __restrict__ V,
                                                     const float* __restrict__ M){
    __shared__ __align__(16) float sK[2][32][72];   // raw K
    __shared__ __align__(16) float sV[2][32][72];   // raw V + ones col 64

    const int bh = blockIdx.x, ch = blockIdx.y;
    const int t = threadIdx.x;
    const int warp = t >> 5, lane = t & 31;
    const int g = lane >> 2, tig = lane & 3;

    const float* Kp = K + ((size_t)bh*Sc + (size_t)ch*CHUNK)*Dc;
    const float* Vp = V + ((size_t)bh*Sc + (size_t)ch*CHUNK)*Dc;
    const float* Mp = M + (size_t)bh*Sc + (size_t)ch*CHUNK;

    // static ones column (exact in tf32) for Ksum n-tile
    if (t < 32){
        #pragma unroll
        for (int buf = 0; buf < 2; buf++){
            sV[buf][t][64] = 1.f;
            #pragma unroll
            for (int c = 65; c < 72; c++) sV[buf][t][c] = 0.f;
        }
    }

    const int srow = t >> 2;          // 0..31
    const int q16 = (t & 3) * 16;     // col quarter
    const u32 skb = smem_u32(&sK[0][0][0]);
    const u32 svb = smem_u32(&sV[0][0][0]);
    const u32 BUFB = 32*72*4;         // bytes per buffer

    // prologue: prefetch blocks 0 and 1
    #pragma unroll
    for (int b = 0; b < 2; b++){
        const float* kr = Kp + (size_t)(b*32 + srow)*Dc + q16;
        const float* vr = Vp + (size_t)(b*32 + srow)*Dc + q16;
        const u32 kd = skb + b*BUFB + (srow*72 + q16)*4;
        const u32 vd = svb + b*BUFB + (srow*72 + q16)*4;
        #pragma unroll
        for (int i = 0; i < 4; i++){
            cp16(kd + 16*i, kr + 4*i);
            cp16(vd + 16*i, vr + 4*i);
        }
        CP_COMMIT();
    }

    float acc[9][4];
    #pragma unroll
    for (int n = 0; n < 9; n++)
        #pragma unroll
        for (int i = 0; i < 4; i++) acc[n][i] = 0.f;

    const int d0 = warp*16;

    #pragma unroll
    for (int b = 0; b < NB; b++){
        const int buf = b & 1;
        if (b < NB-1) asm volatile("cp.async.wait_group 1;" ::: "memory");
        else          asm volatile("cp.async.wait_group 0;" ::: "memory");
        __syncthreads();

        #pragma unroll
        for (int ks = 0; ks < 4; ks++){
            const int s0 = ks*8;
            const float mlo = __ldg(Mp + b*32 + s0 + tig);
            const float mhi = __ldg(Mp + b*32 + s0 + tig + 4);
            u32 a0 = to_tf32(feat(sK[buf][s0+tig  ][d0+g  ]) * mlo);
            u32 a1 = to_tf32(feat(sK[buf][s0+tig  ][d0+g+8]) * mlo);
            u32 a2 = to_tf32(feat(sK[buf][s0+tig+4][d0+g  ]) * mhi);
            u32 a3 = to_tf32(feat(sK[buf][s0+tig+4][d0+g+8]) * mhi);
            #pragma unroll
            for (int nt = 0; nt < 9; nt++){
                u32 b0 = to_tf32(sV[buf][s0+tig  ][nt*8+g]);
                u32 b1 = to_tf32(sV[buf][s0+tig+4][nt*8+g]);
                mma8(acc[nt], a0, a1, a2, a3, b0, b1);
            }
        }
        __syncthreads();

        if (b + 2 < NB){
            const float* kr = Kp + (size_t)((b+2)*32 + srow)*Dc + q16;
            const float* vr = Vp + (size_t)((b+2)*32 + srow)*Dc + q16;
            const u32 kd = skb + buf*BUFB + (srow*72 + q16)*4;
            const u32 vd = svb + buf*BUFB + (srow*72 + q16)*4;
            #pragma unroll
            for (int i = 0; i < 4; i++){
                cp16(kd + 16*i, kr + 4*i);
                cp16(vd + 16*i, vr + 4*i);
            }
        }
        CP_COMMIT();   // commit (possibly empty) keeps group accounting uniform
    }

    // epilogue
    float* dst = g_pKV[ch][bh];
    #pragma unroll
    for (int nt = 0; nt < 8; nt++){
        const int e = nt*8 + 2*tig;
        *(float2*)(dst + (size_t)(d0+g  )*Dc + e) = make_float2(acc[nt][0], acc[nt][1]);
        *(float2*)(dst + (size_t)(d0+g+8)*Dc + e) = make_float2(acc[nt][2], acc[nt][3]);
    }
    if (tig == 0){
        g_pKs[ch][bh][d0+g  ] = acc[8][0];
        g_pKs[ch][bh][d0+g+8] = acc[8][2];
    }
}

// ---------------------------------------------------------------------------
// Reduce partials (f32 out).
// ---------------------------------------------------------------------------
__global__ __launch_bounds__(256) void reduce_kernel(){
    const int bh = blockIdx.x, t = threadIdx.x;
    for (int i = t; i < Dc*Dc; i += 256){
        float s = 0.f;
        #pragma unroll
        for (int c = 0; c < NCHUNK; c++) s += g_pKV[c][bh][i];
        g_KV[bh][i] = s;
    }
    if (t < Dc){
        float s = 0.f;
        #pragma unroll
        for (int c = 0; c < NCHUNK; c++) s += g_pKs[c][bh][t];
        g_Ks[bh][t] = s;
    }
}

// ---------------------------------------------------------------------------
// Phase 2: out[s][e] = Z[s] * sum_d Qf[s][d] KV[d][e]; Z via f32 shfl dot.
// grid (BHc, 16), 256 threads = 8 warps. B-fragments register-resident (RNA).
// Warp (h=w>>2, j=w&3): m-tile parity h, n-tiles {2j, 2j+1}.
// ---------------------------------------------------------------------------
__global__ __launch_bounds__(256) void phase2_kernel(const float* __restrict__ Q,
                                                     float* __restrict__ out){
    __shared__ __align__(16) float sB[64][72];   // KV [d][e] raw f32
    __shared__ __align__(16) u32   sQ[32][68];   // Qf staged as RNA tf32 bits
    __shared__ float sKs[64];
    __shared__ float sZ[32];

    const int bh = blockIdx.x, sb = blockIdx.y;
    const int t = threadIdx.x;
    const int warp = t >> 5, lane = t & 31;
    const int g = lane >> 2, tig = lane & 3;
    const int j = warp & 3, h = warp >> 2;

    // stage KV + Ksum once
    for (int i = t; i < Dc*Dc/4; i += 256){
        const int d = i >> 4, e4 = (i & 15) * 4;
        *(float4*)&sB[d][e4] = *(const float4*)&g_KV[bh][(size_t)d*Dc + e4];
    }
    if (t < Dc) sKs[t] = g_Ks[bh][t];
    __syncthreads();

    // register-resident B fragments (RNA tf32): n-tiles 2j, 2j+1, all 8 k-steps
    const int nt0 = 2*j, nt1 = 2*j + 1;
    u32 bf[8][4];
    #pragma unroll
    for (int ks = 0; ks < 8; ks++){
        const int k0 = ks*8;
        bf[ks][0] = to_tf32(sB[k0+tig  ][nt0*8+g]);
        bf[ks][1] = to_tf32(sB[k0+tig+4][nt0*8+g]);
        bf[ks][2] = to_tf32(sB[k0+tig  ][nt1*8+g]);
        bf[ks][3] = to_tf32(sB[k0+tig+4][nt1*8+g]);
    }

    const float* Qb = Q   + ((size_t)bh*Sc + (size_t)sb*256)*Dc;
    float*       Ob = out + ((size_t)bh*Sc + (size_t)sb*256)*Dc;

    const int srow = t >> 3;          // 0..31
    const int c8 = (t & 7) * 8;

    #pragma unroll 1
    for (int it = 0; it < 8; it++){
        // --- stage 32 Qf rows (tf32 bits) + Z (f32) ---
        {
            const float* qr = Qb + (size_t)(it*32 + srow)*Dc + c8;
            float4 qa = *(const float4*)(qr);
            float4 qb = *(const float4*)(qr + 4);
            float f0 = feat(qa.x), f1 = feat(qa.y), f2 = feat(qa.z), f3 = feat(qa.w);
            float f4 = feat(qb.x), f5 = feat(qb.y), f6 = feat(qb.z), f7 = feat(qb.w);
            float dot = f0*sKs[c8] + f1*sKs[c8+1] + f2*sKs[c8+2] + f3*sKs[c8+3]
                      + f4*sKs[c8+4] + f5*sKs[c8+5] + f6*sKs[c8+6] + f7*sKs[c8+7];
            dot += __shfl_xor_sync(0xffffffffu, dot, 1);
            dot += __shfl_xor_sync(0xffffffffu, dot, 2);
            dot += __shfl_xor_sync(0xffffffffu, dot, 4);
            if ((t & 7) == 0) sZ[srow] = 1.f / dot;
            *(uint4*)&sQ[srow][c8]   = make_uint4(to_tf32(f0), to_tf32(f1), to_tf32(f2), to_tf32(f3));
            *(uint4*)&sQ[srow][c8+4] = make_uint4(to_tf32(f4), to_tf32(f5), to_tf32(f6), to_tf32(f7));
        }
        __syncthreads();

        // --- mma on m-tile (local rows 16h .. 16h+16) ---
        float acc[2][4];
        #pragma unroll
        for (int n = 0; n < 2; n++)
            #pragma unroll
            for (int i = 0; i < 4; i++) acc[n][i] = 0.f;

        const int m0 = 16*h;
        #pragma unroll
        for (int ks = 0; ks < 8; ks++){
            const int k0 = ks*8;
            u32 a0 = sQ[m0+g  ][k0+tig  ];
            u32 a1 = sQ[m0+g+8][k0+tig  ];
            u32 a2 = sQ[m0+g  ][k0+tig+4];
            u32 a3 = sQ[m0+g+8][k0+tig+4];
            mma8(acc[0], a0, a1, a2, a3, bf[ks][0], bf[ks][1]);
            mma8(acc[1], a0, a1, a2, a3, bf[ks][2], bf[ks][3]);
        }

        const float z0 = sZ[m0+g];
        const float z1 = sZ[m0+g+8];
        float* r0 = Ob + (size_t)(it*32 + m0 + g)*Dc;
        float* r1 = Ob + (size_t)(it*32 + m0 + g + 8)*Dc;
        *(float2*)(r0 + nt0*8 + 2*tig) = make_float2(acc[0][0]*z0, acc[0][1]*z0);
        *(float2*)(r1 + nt0*8 + 2*tig) = make_float2(acc[0][2]*z1, acc[0][3]*z1);
        *(float2*)(r0 + nt1*8 + 2*tig) = make_float2(acc[1][0]*z0, acc[1][1]*z0);
        *(float2*)(r1 + nt1*8 + 2*tig) = make_float2(acc[1][2]*z1, acc[1][3]*z1);
        __syncthreads();
    }
}

// ---------------------------------------------------------------------------
extern "C" void kernel_launch(void* const* d_in, const int* in_sizes, int n_in,
                              void* d_out, int out_size){
    const float* Q    = (const float*)d_in[0];
    const float* K    = (const float*)d_in[1];
    const float* V    = (const float*)d_in[2];
    const float* mask = (const float*)d_in[3];
    float* out = (float*)d_out;

    phase1_kernel<<<dim3(BHc, NCHUNK), 128>>>(K, V, mask);
    reduce_kernel<<<BHc, 256>>>();
    phase2_kernel<<<dim3(BHc, 16), 256>>>(Q, out);
}

// round 8
// speedup vs baseline: 2.5558x; 1.0858x over previous
#include <cuda_runtime.h>

typedef unsigned int u32;

#define Sc 4096
#define Dc 64
#define BHc 64
#define NCHUNK 16
#define CHUNK (Sc/NCHUNK)   // 256
#define NB (CHUNK/32)       // 8 blocks of 32 s-rows

__device__ float g_pKV[NCHUNK][BHc][Dc*Dc];  // f32 partial KV
__device__ float g_pKs[NCHUNK][BHc][Dc];     // f32 partial Ksum
__device__ float g_KV[BHc][Dc*Dc];           // reduced KV (f32)
__device__ float g_Ks[BHc][Dc];              // reduced Ksum (f32)

__device__ __forceinline__ u32 to_tf32(float f){
    u32 r; asm("cvt.rna.tf32.f32 %0, %1;" : "=r"(r) : "f"(f)); return r;
}
__device__ __forceinline__ void mma8(float c[4], u32 a0, u32 a1, u32 a2, u32 a3,
                                     u32 b0, u32 b1){
    asm volatile("mma.sync.aligned.m16n8k8.row.col.f32.tf32.tf32.f32 "
        "{%0,%1,%2,%3}, {%4,%5,%6,%7}, {%8,%9}, {%0,%1,%2,%3};"
        : "+f"(c[0]), "+f"(c[1]), "+f"(c[2]), "+f"(c[3])
        : "r"(a0), "r"(a1), "r"(a2), "r"(a3), "r"(b0), "r"(b1));
}
__device__ __forceinline__ float feat(float x){
    return x > 0.f ? x + 1.f : __expf(x);
}
__device__ __forceinline__ u32 smem_u32(const void* p){
    u32 a; asm("{ .reg .u64 t; cvta.to.shared.u64 t, %1; cvt.u32.u64 %0, t; }" : "=r"(a) : "l"(p));
    return a;
}
__device__ __forceinline__ void cp16(u32 dst, const float* src){
    asm volatile("cp.async.cg.shared.global [%0], [%1], 16;" :: "r"(dst), "l"(src) : "memory");
}
#define CP_COMMIT() asm volatile("cp.async.commit_group;" ::: "memory")

// ---------------------------------------------------------------------------
// Phase 1: partial KV[d][e] = sum_s Kf[s][d] V[s][e] (+Ksum via ones column).
// grid (BHc, NCHUNK), 256 threads = 8 warps. Warp w: d-tile (w>>1)*16,
// n-half w&1 (half0: n-tiles {0,1,2,3,8=Ksum}, half1: {4,5,6,7}).
// cp.async double-buffered; one staging-time RNA convert pass per block.
// ---------------------------------------------------------------------------
__global__ __launch_bounds__(256, 5) void phase1_kernel(const float* __restrict__ K,
                                                        const float* __restrict__ V,
                                                        const float* __restrict__ M){
    __shared__ __align__(16) u32 sK[2][32][72];   // raw f32 -> tf32 bits in place
    __shared__ __align__(16) u32 sV[2][32][72];   // cols 64..71 ones-tile (static)

    const int bh = blockIdx.x, ch = blockIdx.y;
    const int t = threadIdx.x;
    const int warp = t >> 5, lane = t & 31;
    const int g = lane >> 2, tig = lane & 3;

    const float* Kp = K + ((size_t)bh*Sc + (size_t)ch*CHUNK)*Dc;
    const float* Vp = V + ((size_t)bh*Sc + (size_t)ch*CHUNK)*Dc;
    const float* Mp = M + (size_t)bh*Sc + (size_t)ch*CHUNK;

    // static ones-column (exact tf32 bits) for Ksum n-tile, both buffers
    if (t < 64){
        const int buf = t >> 5, r = t & 31;
        sV[buf][r][64] = 0x3F800000u;
        #pragma unroll
        for (int c = 65; c < 72; c++) sV[buf][r][c] = 0u;
    }

    const int srow = t >> 3;          // 0..31
    const int c4a = (t & 7) * 4;      // first 16B chunk col
    const int c4b = c4a + 32;         // second chunk col
    const u32 skb = smem_u32(&sK[0][0][0]);
    const u32 svb = smem_u32(&sV[0][0][0]);
    const u32 BUFB = 32*72*4;

    // prologue: prefetch blocks 0,1
    #pragma unroll
    for (int b = 0; b < 2; b++){
        const float* kr = Kp + (size_t)(b*32 + srow)*Dc;
        const float* vr = Vp + (size_t)(b*32 + srow)*Dc;
        const u32 kd = skb + b*BUFB + (srow*72)*4;
        const u32 vd = svb + b*BUFB + (srow*72)*4;
        cp16(kd + c4a*4, kr + c4a);  cp16(kd + c4b*4, kr + c4b);
        cp16(vd + c4a*4, vr + c4a);  cp16(vd + c4b*4, vr + c4b);
        CP_COMMIT();
    }

    float acc[5][4];
    #pragma unroll
    for (int n = 0; n < 5; n++)
        #pragma unroll
        for (int i = 0; i < 4; i++) acc[n][i] = 0.f;

    const int d0 = (warp >> 1) * 16;
    const int nh = warp & 1;

    #pragma unroll
    for (int b = 0; b < NB; b++){
        const int buf = b & 1;
        if (b < NB-1) asm volatile("cp.async.wait_group 1;" ::: "memory");
        else          asm volatile("cp.async.wait_group 0;" ::: "memory");
        __syncthreads();

        // --- staging-time convert (in place): K -> tf32(feat(k)*m), V -> tf32(v)
        {
            const float m = __ldg(Mp + b*32 + srow);
            u32* ka = &sK[buf][srow][c4a];
            u32* kb = &sK[buf][srow][c4b];
            uint4 kx = *(uint4*)ka, ky = *(uint4*)kb;
            *(uint4*)ka = make_uint4(to_tf32(feat(__uint_as_float(kx.x))*m),
                                     to_tf32(feat(__uint_as_float(kx.y))*m),
                                     to_tf32(feat(__uint_as_float(kx.z))*m),
                                     to_tf32(feat(__uint_as_float(kx.w))*m));
            *(uint4*)kb = make_uint4(to_tf32(feat(__uint_as_float(ky.x))*m),
                                     to_tf32(feat(__uint_as_float(ky.y))*m),
                                     to_tf32(feat(__uint_as_float(ky.z))*m),
                                     to_tf32(feat(__uint_as_float(ky.w))*m));
            u32* va = &sV[buf][srow][c4a];
            u32* vb = &sV[buf][srow][c4b];
            uint4 vx = *(uint4*)va, vy = *(uint4*)vb;
            *(uint4*)va = make_uint4(to_tf32(__uint_as_float(vx.x)), to_tf32(__uint_as_float(vx.y)),
                                     to_tf32(__uint_as_float(vx.z)), to_tf32(__uint_as_float(vx.w)));
            *(uint4*)vb = make_uint4(to_tf32(__uint_as_float(vy.x)), to_tf32(__uint_as_float(vy.y)),
                                     to_tf32(__uint_as_float(vy.z)), to_tf32(__uint_as_float(vy.w)));
        }
        __syncthreads();

        // --- pure LDS + MMA ---
        #pragma unroll
        for (int ks = 0; ks < 4; ks++){
            const int s0 = ks*8;
            u32 a0 = sK[buf][s0+tig  ][d0+g  ];
            u32 a1 = sK[buf][s0+tig  ][d0+g+8];
            u32 a2 = sK[buf][s0+tig+4][d0+g  ];
            u32 a3 = sK[buf][s0+tig+4][d0+g+8];
            if (nh == 0){
                #pragma unroll
                for (int i = 0; i < 4; i++){
                    u32 b0 = sV[buf][s0+tig  ][i*8+g];
                    u32 b1 = sV[buf][s0+tig+4][i*8+g];
                    mma8(acc[i], a0, a1, a2, a3, b0, b1);
                }
                u32 b0 = sV[buf][s0+tig  ][64+g];
                u32 b1 = sV[buf][s0+tig+4][64+g];
                mma8(acc[4], a0, a1, a2, a3, b0, b1);
            } else {
                #pragma unroll
                for (int i = 0; i < 4; i++){
                    u32 b0 = sV[buf][s0+tig  ][(4+i)*8+g];
                    u32 b1 = sV[buf][s0+tig+4][(4+i)*8+g];
                    mma8(acc[i], a0, a1, a2, a3, b0, b1);
                }
            }
        }
        __syncthreads();

        if (b + 2 < NB){
            const float* kr = Kp + (size_t)((b+2)*32 + srow)*Dc;
            const float* vr = Vp + (size_t)((b+2)*32 + srow)*Dc;
            const u32 kd = skb + buf*BUFB + (srow*72)*4;
            const u32 vd = svb + buf*BUFB + (srow*72)*4;
            cp16(kd + c4a*4, kr + c4a);  cp16(kd + c4b*4, kr + c4b);
            cp16(vd + c4a*4, vr + c4a);  cp16(vd + c4b*4, vr + c4b);
        }
        CP_COMMIT();
    }

    // epilogue
    float* dst = g_pKV[ch][bh];
    #pragma unroll
    for (int i = 0; i < 4; i++){
        const int e = (nh*4 + i)*8 + 2*tig;
        *(float2*)(dst + (size_t)(d0+g  )*Dc + e) = make_float2(acc[i][0], acc[i][1]);
        *(float2*)(dst + (size_t)(d0+g+8)*Dc + e) = make_float2(acc[i][2], acc[i][3]);
    }
    if (nh == 0 && tig == 0){
        g_pKs[ch][bh][d0+g  ] = acc[4][0];
        g_pKs[ch][bh][d0+g+8] = acc[4][2];
    }
}

// ---------------------------------------------------------------------------
// Reduce partials (f32 out).
// ---------------------------------------------------------------------------
__global__ __launch_bounds__(256) void reduce_kernel(){
    const int bh = blockIdx.x, t = threadIdx.x;
    for (int i = t; i < Dc*Dc; i += 256){
        float s = 0.f;
        #pragma unroll
        for (int c = 0; c < NCHUNK; c++) s += g_pKV[c][bh][i];
        g_KV[bh][i] = s;
    }
    if (t < Dc){
        float s = 0.f;
        #pragma unroll
        for (int c = 0; c < NCHUNK; c++) s += g_pKs[c][bh][t];
        g_Ks[bh][t] = s;
    }
}

// ---------------------------------------------------------------------------
// Phase 2: out[s][e] = Z[s] * sum_d Qf[s][d] KV[d][e]; Z via f32 shfl dot.
// grid (BHc, 16), 256 threads. B-fragments register-resident (RNA, once).
// Q staged double-buffered; next tile's LDGs issued before current MMAs.
// Warp (h=w>>2, j=w&3): m-tile 16h, n-tiles {2j, 2j+1}.
// ---------------------------------------------------------------------------
__global__ __launch_bounds__(256, 4) void phase2_kernel(const float* __restrict__ Q,
                                                        float* __restrict__ out){
    __shared__ __align__(16) float sB[64][72];    // KV [d][e] raw f32
    __shared__ __align__(16) u32   sQd[2][32][68];// Qf RNA tf32 bits, double buffered
    __shared__ float sKs[64];
    __shared__ float sZ[2][32];

    const int bh = blockIdx.x, sb = blockIdx.y;
    const int t = threadIdx.x;
    const int warp = t >> 5, lane = t & 31;
    const int g = lane >> 2, tig = lane & 3;
    const int j = warp & 3, h = warp >> 2;

    // stage KV + Ksum once
    for (int i = t; i < Dc*Dc/4; i += 256){
        const int d = i >> 4, e4 = (i & 15) * 4;
        *(float4*)&sB[d][e4] = *(const float4*)&g_KV[bh][(size_t)d*Dc + e4];
    }
    if (t < Dc) sKs[t] = g_Ks[bh][t];
    __syncthreads();

    // register-resident B fragments (RNA tf32), n-tiles 2j and 2j+1
    const int nt0 = 2*j, nt1 = 2*j + 1;
    u32 bf[8][4];
    #pragma unroll
    for (int ks = 0; ks < 8; ks++){
        const int k0 = ks*8;
        bf[ks][0] = to_tf32(sB[k0+tig  ][nt0*8+g]);
        bf[ks][1] = to_tf32(sB[k0+tig+4][nt0*8+g]);
        bf[ks][2] = to_tf32(sB[k0+tig  ][nt1*8+g]);
        bf[ks][3] = to_tf32(sB[k0+tig+4][nt1*8+g]);
    }

    const float* Qb = Q   + ((size_t)bh*Sc + (size_t)sb*256)*Dc;
    float*       Ob = out + ((size_t)bh*Sc + (size_t)sb*256)*Dc;

    const int srow = t >> 3;          // 0..31
    const int c8 = (t & 7) * 8;

    // prologue: stage tile 0
    {
        const float* qr = Qb + (size_t)srow*Dc + c8;
        float4 qa = *(const float4*)(qr);
        float4 qb = *(const float4*)(qr + 4);
        float f0 = feat(qa.x), f1 = feat(qa.y), f2 = feat(qa.z), f3 = feat(qa.w);
        float f4 = feat(qb.x), f5 = feat(qb.y), f6 = feat(qb.z), f7 = feat(qb.w);
        float dot = f0*sKs[c8] + f1*sKs[c8+1] + f2*sKs[c8+2] + f3*sKs[c8+3]
                  + f4*sKs[c8+4] + f5*sKs[c8+5] + f6*sKs[c8+6] + f7*sKs[c8+7];
        dot += __shfl_xor_sync(0xffffffffu, dot, 1);
        dot += __shfl_xor_sync(0xffffffffu, dot, 2);
        dot += __shfl_xor_sync(0xffffffffu, dot, 4);
        if ((t & 7) == 0) sZ[0][srow] = 1.f / dot;
        *(uint4*)&sQd[0][srow][c8]   = make_uint4(to_tf32(f0), to_tf32(f1), to_tf32(f2), to_tf32(f3));
        *(uint4*)&sQd[0][srow][c8+4] = make_uint4(to_tf32(f4), to_tf32(f5), to_tf32(f6), to_tf32(f7));
    }
    __syncthreads();

    #pragma unroll 1
    for (int it = 0; it < 8; it++){
        const int buf = it & 1;

        // issue next tile's loads before compute (latency overlap)
        float4 qa, qb;
        if (it < 7){
            const float* qr = Qb + (size_t)((it+1)*32 + srow)*Dc + c8;
            qa = *(const float4*)(qr);
            qb = *(const float4*)(qr + 4);
        }

        // --- mma on this warp's m-tile ---
        float acc[2][4];
        #pragma unroll
        for (int n = 0; n < 2; n++)
            #pragma unroll
            for (int i = 0; i < 4; i++) acc[n][i] = 0.f;

        const int m0 = 16*h;
        #pragma unroll
        for (int ks = 0; ks < 8; ks++){
            const int k0 = ks*8;
            u32 a0 = sQd[buf][m0+g  ][k0+tig  ];
            u32 a1 = sQd[buf][m0+g+8][k0+tig  ];
            u32 a2 = sQd[buf][m0+g  ][k0+tig+4];
            u32 a3 = sQd[buf][m0+g+8][k0+tig+4];
            mma8(acc[0], a0, a1, a2, a3, bf[ks][0], bf[ks][1]);
            mma8(acc[1], a0, a1, a2, a3, bf[ks][2], bf[ks][3]);
        }

        const float z0 = sZ[buf][m0+g];
        const float z1 = sZ[buf][m0+g+8];
        float* r0 = Ob + (size_t)(it*32 + m0 + g)*Dc;
        float* r1 = Ob + (size_t)(it*32 + m0 + g + 8)*Dc;
        *(float2*)(r0 + nt0*8 + 2*tig) = make_float2(acc[0][0]*z0, acc[0][1]*z0);
        *(float2*)(r1 + nt0*8 + 2*tig) = make_float2(acc[0][2]*z1, acc[0][3]*z1);
        *(float2*)(r0 + nt1*8 + 2*tig) = make_float2(acc[1][0]*z0, acc[1][1]*z0);
        *(float2*)(r1 + nt1*8 + 2*tig) = make_float2(acc[1][2]*z1, acc[1][3]*z1);

        // stage next tile into other buffer
        if (it < 7){
            float f0 = feat(qa.x), f1 = feat(qa.y), f2 = feat(qa.z), f3 = feat(qa.w);
            float f4 = feat(qb.x), f5 = feat(qb.y), f6 = feat(qb.z), f7 = feat(qb.w);
            float dot = f0*sKs[c8] + f1*sKs[c8+1] + f2*sKs[c8+2] + f3*sKs[c8+3]
                      + f4*sKs[c8+4] + f5*sKs[c8+5] + f6*sKs[c8+6] + f7*sKs[c8+7];
            dot += __shfl_xor_sync(0xffffffffu, dot, 1);
            dot += __shfl_xor_sync(0xffffffffu, dot, 2);
            dot += __shfl_xor_sync(0xffffffffu, dot, 4);
            if ((t & 7) == 0) sZ[buf^1][srow] = 1.f / dot;
            *(uint4*)&sQd[buf^1][srow][c8]   = make_uint4(to_tf32(f0), to_tf32(f1), to_tf32(f2), to_tf32(f3));
            *(uint4*)&sQd[buf^1][srow][c8+4] = make_uint4(to_tf32(f4), to_tf32(f5), to_tf32(f6), to_tf32(f7));
        }
        __syncthreads();
    }
}

// ---------------------------------------------------------------------------
extern "C" void kernel_launch(void* const* d_in, const int* in_sizes, int n_in,
                              void* d_out, int out_size){
    const float* Q    = (const float*)d_in[0];
    const float* K    = (const float*)d_in[1];
    const float* V    = (const float*)d_in[2];
    const float* mask = (const float*)d_in[3];
    float* out = (float*)d_out;

    phase1_kernel<<<dim3(BHc, NCHUNK), 256>>>(K, V, mask);
    reduce_kernel<<<BHc, 256>>>();
    phase2_kernel<<<dim3(BHc, 16), 256>>>(Q, out);
}